// round 11
// baseline (speedup 1.0000x reference)
#include <cuda_runtime.h>
#include <cuda_fp16.h>
#include <cstddef>

#define NB 2
#define NC 128
#define TWOC 256
#define NE 60000
#define ETILES (NE / 32)                       // 1875
#define TRB_HALF (2 * 2 * ETILES)              // 7500 tiles per batch
#define W_WARPS (2 * NC * 15 + 3)
#define W_BLOCKS ((W_WARPS + 7) / 8)           // 481
#define ZQ (3 * NE / 4)                        // 45000 float4 per half
#define Z_BLOCKS ((ZQ + 255) / 256)            // 176
#define GROUPS4B (NE / 4)                      // 15000 groups per batch

// Transposed inputs in fp16, tensor-interleaved: [b][e][tensor][c]
__device__ __half g_xti[(size_t)NB * NE * TWOC];
// Effective fused weights: [branch][c][s*3+k] padded to 16
__device__ float g_V[2][NC][16];
__device__ float g_cb[3];

// ---------------------------------------------------------------------------
// Prep for ONE batch: transpose tiles (+weights if do_weights) + zero out half
// ---------------------------------------------------------------------------
__global__ void __launch_bounds__(256)
prep_kernel(const float* __restrict__ x0, const float* __restrict__ x1,
    const float* __restrict__ Wa_local, const float* __restrict__ ba_local,
    const float* __restrict__ Wb_local, const float* __restrict__ bb_local,
    const float* __restrict__ Wa_tri,   const float* __restrict__ ba_tri,
    const float* __restrict__ Wb_tri,   const float* __restrict__ bb_tri,
    const float* __restrict__ Wa_fuse,  const float* __restrict__ ba_fuse,
    const float* __restrict__ Wb_fuse,  const float* __restrict__ bb_fuse,
    float* __restrict__ out, int b, int do_weights)
{
    if (blockIdx.x < TRB_HALF) {
        __shared__ __half tile[32][66];
        int bx = blockIdx.x;
        const int eb = bx % ETILES;
        const int ch = (bx / ETILES) & 1;
        const int tensor = bx / (2 * ETILES);
        const float* __restrict__ src = tensor ? x1 : x0;
        const int e0 = eb * 32, c0 = ch * 64;
        const int tx = threadIdx.x & 31;
        const int ty = threadIdx.x >> 5;

#pragma unroll
        for (int i = 0; i < 8; i++) {
            int cl = ty + 8 * i;
            tile[tx][cl] = __float2half_rn(
                src[((size_t)b * NC + c0 + cl) * NE + e0 + tx]);
        }
        __syncthreads();
#pragma unroll
        for (int it = 0; it < 4; it++) {
            int e = ty * 4 + it;
            unsigned v = *reinterpret_cast<const unsigned*>(&tile[e][2 * tx]);
            *reinterpret_cast<unsigned*>(
                g_xti + ((size_t)(b * NE + e0 + e)) * TWOC
                      + tensor * NC + c0 + 2 * tx) = v;
        }
        return;
    }

    const int zbase = TRB_HALF + (do_weights ? W_BLOCKS : 0);
    if (blockIdx.x >= zbase) {
        // zero this batch's half of out: 3*NE floats = ZQ float4 (exact)
        int i = (blockIdx.x - zbase) * 256 + threadIdx.x;
        if (i < ZQ)
            reinterpret_cast<float4*>(out)[(size_t)b * ZQ + i] =
                make_float4(0.f, 0.f, 0.f, 0.f);
        return;
    }

    // ---- weight folding (only in the do_weights launch) ----
    const int lane = threadIdx.x & 31;
    const int w = (blockIdx.x - TRB_HALF) * 8 + (threadIdx.x >> 5);

    if (w < 2 * NC * 15) {
        const int t   = w / (NC * 15);
        const int rem = w - t * (NC * 15);
        const int c   = rem / 15;
        const int sk  = rem - c * 15;
        const int s   = sk / 3;
        const int k   = sk - s * 3;
        const float* Wf = t ? Wb_fuse  : Wa_fuse;
        const float* Wt = t ? Wb_tri   : Wa_tri;
        const float* Wl = t ? Wb_local : Wa_local;
        float acc = 0.f;
#pragma unroll
        for (int j = 0; j < 4; j++) {
            int o = lane + 32 * j;
            acc = fmaf(Wf[k * (2 * NC) + NC + o], Wt[(o * NC + c) * 5 + s], acc);
            if (s == 0)
                acc = fmaf(Wf[k * (2 * NC) + o], Wl[o * NC + c], acc);
        }
#pragma unroll
        for (int off = 16; off; off >>= 1)
            acc += __shfl_xor_sync(0xffffffffu, acc, off);
        if (lane == 0) {
            g_V[t][c][sk] = acc;
            if (sk == 0) g_V[t][c][15] = 0.f;
        }
    } else if (w < 2 * NC * 15 + 3) {
        const int k = w - 2 * NC * 15;
        float acc = 0.f;
#pragma unroll
        for (int j = 0; j < 4; j++) {
            int o = lane + 32 * j;
            acc = fmaf(Wa_fuse[k * 2 * NC + o],      ba_local[o], acc);
            acc = fmaf(Wa_fuse[k * 2 * NC + NC + o], ba_tri[o],   acc);
            acc = fmaf(Wb_fuse[k * 2 * NC + o],      bb_local[o], acc);
            acc = fmaf(Wb_fuse[k * 2 * NC + NC + o], bb_tri[o],   acc);
        }
#pragma unroll
        for (int off = 16; off; off >>= 1)
            acc += __shfl_xor_sync(0xffffffffu, acc, off);
        if (lane == 0)
            g_cb[k] = acc + ba_fuse[k] + bb_fuse[k];
    }
}

// ---------------------------------------------------------------------------
// Main gather + fused dot for ONE batch. Warp owns one tensor of a 4-edge
// group; lane owns 4 channels (30 weight regs, 24 warps/SM). Partials
// combined via atomicAdd (2 deterministic contributors; out pre-zeroed).
// ---------------------------------------------------------------------------
__device__ __forceinline__ __half2 u2h(const unsigned& u)
{
    return *reinterpret_cast<const __half2*>(&u);
}

__device__ __forceinline__ void edge_dot(
    const uint2 r0, const uint2 r1, const uint2 r2,
    const uint2 r3, const uint2 r4,
    const __half2 Vp[2][15], float* __restrict__ res)
{
    __half2 n1a = u2h(r1.x), n1b = u2h(r1.y);
    __half2 n2a = u2h(r2.x), n2b = u2h(r2.y);
    __half2 n3a = u2h(r3.x), n3b = u2h(r3.y);
    __half2 n4a = u2h(r4.x), n4b = u2h(r4.y);

    __half2 Ga[5], Gb[5];
    Ga[0] = u2h(r0.x);
    Gb[0] = u2h(r0.y);
    Ga[1] = __hadd2(n1a, n3a);  Gb[1] = __hadd2(n1b, n3b);
    Ga[2] = __hadd2(n2a, n4a);  Gb[2] = __hadd2(n2b, n4b);
    Ga[3] = __habs2(__hsub2(n1a, n3a));  Gb[3] = __habs2(__hsub2(n1b, n3b));
    Ga[4] = __habs2(__hsub2(n2a, n4a));  Gb[4] = __habs2(__hsub2(n2b, n4b));

    __half2 A0 = __hmul2(Vp[0][0], Ga[0]);
    __half2 A1 = __hmul2(Vp[0][1], Ga[0]);
    __half2 A2 = __hmul2(Vp[0][2], Ga[0]);
    __half2 B0 = __hmul2(Vp[1][0], Gb[0]);
    __half2 B1 = __hmul2(Vp[1][1], Gb[0]);
    __half2 B2 = __hmul2(Vp[1][2], Gb[0]);
#pragma unroll
    for (int s = 1; s < 5; s++) {
        A0 = __hfma2(Vp[0][s * 3 + 0], Ga[s], A0);
        A1 = __hfma2(Vp[0][s * 3 + 1], Ga[s], A1);
        A2 = __hfma2(Vp[0][s * 3 + 2], Ga[s], A2);
        B0 = __hfma2(Vp[1][s * 3 + 0], Gb[s], B0);
        B1 = __hfma2(Vp[1][s * 3 + 1], Gb[s], B1);
        B2 = __hfma2(Vp[1][s * 3 + 2], Gb[s], B2);
    }
    float2 a0 = __half22float2(A0), b0 = __half22float2(B0);
    float2 a1 = __half22float2(A1), b1 = __half22float2(B1);
    float2 a2 = __half22float2(A2), b2 = __half22float2(B2);
    res[0] = (a0.x + a0.y) + (b0.x + b0.y);
    res[1] = (a1.x + a1.y) + (b1.x + b1.y);
    res[2] = (a2.x + a2.y) + (b2.x + b2.y);
}

__device__ __forceinline__ void do_pair(
    const __half* __restrict__ base,
    int e, const int4 gi0, const int4 gi1,
    const __half2 Vp[2][15], float* __restrict__ res)
{
    uint2 a0 = *reinterpret_cast<const uint2*>(base + (size_t)e     * TWOC);
    uint2 a1 = *reinterpret_cast<const uint2*>(base + (size_t)gi0.x * TWOC);
    uint2 a2 = *reinterpret_cast<const uint2*>(base + (size_t)gi0.y * TWOC);
    uint2 a3 = *reinterpret_cast<const uint2*>(base + (size_t)gi0.z * TWOC);
    uint2 a4 = *reinterpret_cast<const uint2*>(base + (size_t)gi0.w * TWOC);
    uint2 c0 = *reinterpret_cast<const uint2*>(base + (size_t)(e+1) * TWOC);
    uint2 c1 = *reinterpret_cast<const uint2*>(base + (size_t)gi1.x * TWOC);
    uint2 c2 = *reinterpret_cast<const uint2*>(base + (size_t)gi1.y * TWOC);
    uint2 c3 = *reinterpret_cast<const uint2*>(base + (size_t)gi1.z * TWOC);
    uint2 c4 = *reinterpret_cast<const uint2*>(base + (size_t)gi1.w * TWOC);

    edge_dot(a0, a1, a2, a3, a4, Vp, res);
    edge_dot(c0, c1, c2, c3, c4, Vp, res + 3);
}

__global__ void __launch_bounds__(256, 3)
mesh_main_kernel(const int* __restrict__ gemm, float* __restrict__ out, int b)
{
    const int lane = threadIdx.x & 31;
    const int W    = blockIdx.x * 8 + (threadIdx.x >> 5);
    const int t    = W & 1;
    const int g0   = W >> 1;
    const int GS   = (gridDim.x * 8) >> 1;

    __half2 Vp[2][15];
#pragma unroll
    for (int j = 0; j < 2; j++) {
        const float* r0 = g_V[t][4 * lane + 2 * j];
        const float* r1 = g_V[t][4 * lane + 2 * j + 1];
#pragma unroll
        for (int sk = 0; sk < 15; sk++)
            Vp[j][sk] = __floats2half2_rn(r0[sk], r1[sk]);
    }
    float cbk = (t == 0 && lane < 12) ? g_cb[lane % 3] : 0.f;

    const int4* __restrict__ gi4 =
        reinterpret_cast<const int4*>(gemm) + (size_t)b * NE;
    const __half* __restrict__ xb =
        g_xti + (size_t)b * NE * TWOC + t * NC + lane * 4;
    float* __restrict__ ob = out + (size_t)b * 3 * NE;

    for (int g = g0; g < GROUPS4B; g += GS) {
        const int eb = 4 * g;
        const int4 gA = gi4[eb];
        const int4 gB = gi4[eb + 1];
        const int4 gC = gi4[eb + 2];
        const int4 gD = gi4[eb + 3];

        float res[12];
        do_pair(xb, eb,     gA, gB, Vp, res);
        do_pair(xb, eb + 2, gC, gD, Vp, res + 6);

#pragma unroll
        for (int off = 16; off; off >>= 1)
#pragma unroll
            for (int r = 0; r < 12; r++)
                res[r] += __shfl_xor_sync(0xffffffffu, res[r], off);

        if (lane < 12) {
            const int u = lane / 3;
            const int k = lane - 3 * u;
            atomicAdd(ob + (size_t)k * NE + eb + u, res[lane] + cbk);
        }
    }
}

// ---------------------------------------------------------------------------
extern "C" void kernel_launch(void* const* d_in, const int* in_sizes, int n_in,
                              void* d_out, int out_size)
{
    const float* x_0      = (const float*)d_in[0];
    const float* x_1      = (const float*)d_in[1];
    const int*   gemm     = (const int*)  d_in[2];
    const float* Wa_local = (const float*)d_in[3];
    const float* ba_local = (const float*)d_in[4];
    const float* Wb_local = (const float*)d_in[5];
    const float* bb_local = (const float*)d_in[6];
    const float* Wa_tri   = (const float*)d_in[7];
    const float* ba_tri   = (const float*)d_in[8];
    const float* Wb_tri   = (const float*)d_in[9];
    const float* bb_tri   = (const float*)d_in[10];
    const float* Wa_fuse  = (const float*)d_in[11];
    const float* ba_fuse  = (const float*)d_in[12];
    const float* Wb_fuse  = (const float*)d_in[13];
    const float* bb_fuse  = (const float*)d_in[14];
    float* out = (float*)d_out;

    cudaStream_t s0 = (cudaStream_t)0;

    // fork/join resources (created per call; few calls total, never destroyed
    // to stay legal while capture is active)
    cudaStream_t s2;
    cudaStreamCreateWithFlags(&s2, cudaStreamNonBlocking);
    cudaEvent_t evA, evC;
    cudaEventCreateWithFlags(&evA, cudaEventDisableTiming);
    cudaEventCreateWithFlags(&evC, cudaEventDisableTiming);

    // prep batch 0 (+ weights + zero half 0) on stream 0
    prep_kernel<<<TRB_HALF + W_BLOCKS + Z_BLOCKS, 256, 0, s0>>>(
        x_0, x_1,
        Wa_local, ba_local, Wb_local, bb_local,
        Wa_tri, ba_tri, Wb_tri, bb_tri,
        Wa_fuse, ba_fuse, Wb_fuse, bb_fuse,
        out, 0, 1);
    cudaEventRecord(evA, s0);

    // prep batch 1 on stream 0 (overlaps main b=0 on s2)
    prep_kernel<<<TRB_HALF + Z_BLOCKS, 256, 0, s0>>>(
        x_0, x_1,
        Wa_local, ba_local, Wb_local, bb_local,
        Wa_tri, ba_tri, Wb_tri, bb_tri,
        Wa_fuse, ba_fuse, Wb_fuse, bb_fuse,
        out, 1, 0);

    // main b=0 on s2, after prep batch 0
    cudaStreamWaitEvent(s2, evA, 0);
    mesh_main_kernel<<<296, 256, 0, s2>>>(gemm, out, 0);
    cudaEventRecord(evC, s2);

    // main b=1 on stream 0, after prep batch 1
    mesh_main_kernel<<<296, 256, 0, s0>>>(gemm, out, 1);

    // join s2 back into stream 0
    cudaStreamWaitEvent(s0, evC, 0);
}

// round 12
// speedup vs baseline: 1.2027x; 1.2027x over previous
#include <cuda_runtime.h>
#include <cuda_fp16.h>
#include <cstddef>

#define NB 2
#define NC 128
#define TWOC 256
#define NE 60000
#define TR_BLOCKS (2 * NB * 2 * (NE / 32))          // 15000 transpose tiles
#define W_WARPS   (2 * NC * 15 + 3)
#define W_BLOCKS  ((W_WARPS + 7) / 8)
#define GROUPS2   (NB * NE / 2)                      // 60000 2-edge groups
#define STAGE_BYTES 5120                             // 10 rows x 512B
#define WARP_BUF    (2 * STAGE_BYTES)                // double buffered
#define SMEM_MAIN   (8 * WARP_BUF)                   // 81920 B per block

// Transposed inputs in fp16, tensor-interleaved: [b][e][tensor][c] (512B/edge)
__device__ __half g_xti[(size_t)NB * NE * TWOC];
// Effective fused weights: [branch][c][s*3+k] padded to 16
__device__ float g_V[2][NC][16];
__device__ float g_cb[3];

// ---------------------------------------------------------------------------
// Kernel 1 (fused): transpose x->fp16 interleaved + weight folding.
// ---------------------------------------------------------------------------
__global__ void __launch_bounds__(256)
prep_kernel(const float* __restrict__ x0, const float* __restrict__ x1,
    const float* __restrict__ Wa_local, const float* __restrict__ ba_local,
    const float* __restrict__ Wb_local, const float* __restrict__ bb_local,
    const float* __restrict__ Wa_tri,   const float* __restrict__ ba_tri,
    const float* __restrict__ Wb_tri,   const float* __restrict__ bb_tri,
    const float* __restrict__ Wa_fuse,  const float* __restrict__ ba_fuse,
    const float* __restrict__ Wb_fuse,  const float* __restrict__ bb_fuse)
{
    if (blockIdx.x < TR_BLOCKS) {
        __shared__ __half tile[32][66];
        int bx = blockIdx.x;
        const int eb = bx % (NE / 32);  bx /= (NE / 32);
        const int ch = bx & 1;          bx >>= 1;
        const int b  = bx & 1;
        const int tensor = bx >> 1;
        const float* __restrict__ src = tensor ? x1 : x0;
        const int e0 = eb * 32, c0 = ch * 64;
        const int tx = threadIdx.x & 31;
        const int ty = threadIdx.x >> 5;

#pragma unroll
        for (int i = 0; i < 8; i++) {
            int cl = ty + 8 * i;
            tile[tx][cl] = __float2half_rn(
                src[((size_t)b * NC + c0 + cl) * NE + e0 + tx]);
        }
        __syncthreads();
#pragma unroll
        for (int it = 0; it < 4; it++) {
            int e = ty * 4 + it;
            unsigned v = *reinterpret_cast<const unsigned*>(&tile[e][2 * tx]);
            *reinterpret_cast<unsigned*>(
                g_xti + ((size_t)(b * NE + e0 + e)) * TWOC
                      + tensor * NC + c0 + 2 * tx) = v;
        }
        return;
    }

    const int lane = threadIdx.x & 31;
    const int w = (blockIdx.x - TR_BLOCKS) * 8 + (threadIdx.x >> 5);

    if (w < 2 * NC * 15) {
        const int t   = w / (NC * 15);
        const int rem = w - t * (NC * 15);
        const int c   = rem / 15;
        const int sk  = rem - c * 15;
        const int s   = sk / 3;
        const int k   = sk - s * 3;
        const float* Wf = t ? Wb_fuse  : Wa_fuse;
        const float* Wt = t ? Wb_tri   : Wa_tri;
        const float* Wl = t ? Wb_local : Wa_local;
        float acc = 0.f;
#pragma unroll
        for (int j = 0; j < 4; j++) {
            int o = lane + 32 * j;
            acc = fmaf(Wf[k * (2 * NC) + NC + o], Wt[(o * NC + c) * 5 + s], acc);
            if (s == 0)
                acc = fmaf(Wf[k * (2 * NC) + o], Wl[o * NC + c], acc);
        }
#pragma unroll
        for (int off = 16; off; off >>= 1)
            acc += __shfl_xor_sync(0xffffffffu, acc, off);
        if (lane == 0) {
            g_V[t][c][sk] = acc;
            if (sk == 0) g_V[t][c][15] = 0.f;
        }
    } else if (w < 2 * NC * 15 + 3) {
        const int k = w - 2 * NC * 15;
        float acc = 0.f;
#pragma unroll
        for (int j = 0; j < 4; j++) {
            int o = lane + 32 * j;
            acc = fmaf(Wa_fuse[k * 2 * NC + o],      ba_local[o], acc);
            acc = fmaf(Wa_fuse[k * 2 * NC + NC + o], ba_tri[o],   acc);
            acc = fmaf(Wb_fuse[k * 2 * NC + o],      bb_local[o], acc);
            acc = fmaf(Wb_fuse[k * 2 * NC + NC + o], bb_tri[o],   acc);
        }
#pragma unroll
        for (int off = 16; off; off >>= 1)
            acc += __shfl_xor_sync(0xffffffffu, acc, off);
        if (lane == 0)
            g_cb[k] = acc + ba_fuse[k] + bb_fuse[k];
    }
}

// ---------------------------------------------------------------------------
// Kernel 2: cp.async-pipelined gather + fused dot.
// Warp owns a 2-edge group (both tensors). 10 rows (512B each) per group
// staged through a 2-deep smem ring via cp.async.cg; compute reads LDS.128.
// Lane mapping (R9): lane<16 -> tensor0 channels 8L.., lane>=16 -> tensor1.
// ---------------------------------------------------------------------------
__device__ __forceinline__ unsigned smem_u32(const void* p)
{
    unsigned a;
    asm("{ .reg .u64 t; cvta.to.shared.u64 t, %1; cvt.u32.u64 %0, t; }"
        : "=r"(a) : "l"(p));
    return a;
}

__device__ __forceinline__ __half2 u2h(const unsigned& u)
{
    return *reinterpret_cast<const __half2*>(&u);
}

__device__ __forceinline__ void edge_dot(
    const uint4 r0, const uint4 r1, const uint4 r2,
    const uint4 r3, const uint4 r4,
    const __half2 Vp[4][15], float* __restrict__ res)
{
    const __half2 z = __float2half2_rn(0.f);
    __half2 A0 = z, A1 = z, A2 = z, B0 = z, B1 = z, B2 = z;

#define DO_SLOT(j, X0, X1, X2, X3, X4, P0, P1, P2)                        \
    {                                                                     \
        __half2 G0 = u2h(X0);                                             \
        __half2 n1 = u2h(X1), n2 = u2h(X2), n3 = u2h(X3), n4 = u2h(X4);   \
        __half2 G1 = __hadd2(n1, n3), G2 = __hadd2(n2, n4);               \
        __half2 G3 = __habs2(__hsub2(n1, n3));                            \
        __half2 G4 = __habs2(__hsub2(n2, n4));                            \
        P0 = __hfma2(Vp[j][0],  G0, P0);                                  \
        P1 = __hfma2(Vp[j][1],  G0, P1);                                  \
        P2 = __hfma2(Vp[j][2],  G0, P2);                                  \
        P0 = __hfma2(Vp[j][3],  G1, P0);                                  \
        P1 = __hfma2(Vp[j][4],  G1, P1);                                  \
        P2 = __hfma2(Vp[j][5],  G1, P2);                                  \
        P0 = __hfma2(Vp[j][6],  G2, P0);                                  \
        P1 = __hfma2(Vp[j][7],  G2, P1);                                  \
        P2 = __hfma2(Vp[j][8],  G2, P2);                                  \
        P0 = __hfma2(Vp[j][9],  G3, P0);                                  \
        P1 = __hfma2(Vp[j][10], G3, P1);                                  \
        P2 = __hfma2(Vp[j][11], G3, P2);                                  \
        P0 = __hfma2(Vp[j][12], G4, P0);                                  \
        P1 = __hfma2(Vp[j][13], G4, P1);                                  \
        P2 = __hfma2(Vp[j][14], G4, P2);                                  \
    }

    DO_SLOT(0, r0.x, r1.x, r2.x, r3.x, r4.x, A0, A1, A2)
    DO_SLOT(1, r0.y, r1.y, r2.y, r3.y, r4.y, A0, A1, A2)
    DO_SLOT(2, r0.z, r1.z, r2.z, r3.z, r4.z, B0, B1, B2)
    DO_SLOT(3, r0.w, r1.w, r2.w, r3.w, r4.w, B0, B1, B2)
#undef DO_SLOT

    float2 a0 = __half22float2(A0), b0 = __half22float2(B0);
    float2 a1 = __half22float2(A1), b1 = __half22float2(B1);
    float2 a2 = __half22float2(A2), b2 = __half22float2(B2);
    res[0] = (a0.x + a0.y) + (b0.x + b0.y);
    res[1] = (a1.x + a1.y) + (b1.x + b1.y);
    res[2] = (a2.x + a2.y) + (b2.x + b2.y);
}

// issue 10 rows of group (b, eb) into stage buffer at smem addr d0
__device__ __forceinline__ void issue_group(
    int b, int eb, const int4 ga, const int4 gb,
    unsigned d0, int lane)
{
    const char* base = reinterpret_cast<const char*>(g_xti)
                     + (size_t)b * NE * 512 + lane * 16;
    const int rows[10] = { eb,     ga.x, ga.y, ga.z, ga.w,
                           eb + 1, gb.x, gb.y, gb.z, gb.w };
#pragma unroll
    for (int r = 0; r < 10; r++) {
        const char* src = base + (size_t)rows[r] * 512;
        asm volatile("cp.async.cg.shared.global [%0], [%1], 16;"
                     :: "r"(d0 + r * 512), "l"(src) : "memory");
    }
    asm volatile("cp.async.commit_group;" ::: "memory");
}

__global__ void __launch_bounds__(256, 2)
mesh_main_kernel(const int* __restrict__ gemm, float* __restrict__ out)
{
    extern __shared__ char sm_buf[];
    const int lane = threadIdx.x & 31;
    const int wid  = threadIdx.x >> 5;
    char* buf = sm_buf + wid * WARP_BUF;
    const unsigned buf_u32 = smem_u32(buf) + lane * 16;

    // lane's tensor + channel base; weights: 60 half2 regs
    const int lt = lane >> 4;
    const int lc = (lane & 15) * 8;
    __half2 Vp[4][15];
#pragma unroll
    for (int j = 0; j < 4; j++) {
        const float* r0 = g_V[lt][lc + 2 * j];
        const float* r1 = g_V[lt][lc + 2 * j + 1];
#pragma unroll
        for (int sk = 0; sk < 15; sk++)
            Vp[j][sk] = __floats2half2_rn(r0[sk], r1[sk]);
    }
    float cbk = (lane < 6) ? g_cb[lane % 3] : 0.f;

    const int4* __restrict__ gi4 = reinterpret_cast<const int4*>(gemm);
    const int gw = blockIdx.x * 8 + wid;
    const int W  = gridDim.x * 8;

    // current group
    int g  = gw;
    int b  = (2 * g >= NE) ? 1 : 0;
    int eb = 2 * g - b * NE;
    {
        int4 ga = gi4[(size_t)b * NE + eb];
        int4 gb = gi4[(size_t)b * NE + eb + 1];
        issue_group(b, eb, ga, gb, buf_u32, lane);
    }

    // next group's indices (clamped)
    int gn  = g + W;
    int gnc = (gn < GROUPS2) ? gn : gw;
    int bn  = (2 * gnc >= NE) ? 1 : 0;
    int ebn = 2 * gnc - bn * NE;
    int4 gan = gi4[(size_t)bn * NE + ebn];
    int4 gbn = gi4[(size_t)bn * NE + ebn + 1];

    int s = 0;
    while (true) {
        const bool has_next = (g + W) < GROUPS2;

        // issue next group into the other stage
        issue_group(bn, ebn, gan, gbn, buf_u32 + (s ^ 1) * STAGE_BYTES, lane);

        // prefetch indices two groups ahead
        const int gn2  = g + 2 * W;
        const int gn2c = (gn2 < GROUPS2) ? gn2 : gw;
        const int bn2  = (2 * gn2c >= NE) ? 1 : 0;
        const int ebn2 = 2 * gn2c - bn2 * NE;
        const int4 ga2 = gi4[(size_t)bn2 * NE + ebn2];
        const int4 gb2 = gi4[(size_t)bn2 * NE + ebn2 + 1];

        // wait for the current stage's data, make visible warp-wide
        asm volatile("cp.async.wait_group 1;" ::: "memory");
        __syncwarp();

        // compute current stage
        float res[6];
#pragma unroll
        for (int u = 0; u < 2; u++) {
            const char* p = buf + s * STAGE_BYTES + u * 5 * 512 + lane * 16;
            uint4 r0 = *reinterpret_cast<const uint4*>(p);
            uint4 r1 = *reinterpret_cast<const uint4*>(p + 512);
            uint4 r2 = *reinterpret_cast<const uint4*>(p + 1024);
            uint4 r3 = *reinterpret_cast<const uint4*>(p + 1536);
            uint4 r4 = *reinterpret_cast<const uint4*>(p + 2048);
            edge_dot(r0, r1, r2, r3, r4, Vp, res + 3 * u);
        }

#pragma unroll
        for (int off = 16; off; off >>= 1)
#pragma unroll
            for (int r = 0; r < 6; r++)
                res[r] += __shfl_xor_sync(0xffffffffu, res[r], off);

        if (lane < 6) {
            const int u = lane / 3;
            const int k = lane - 3 * u;
            out[((size_t)b * 3 + k) * NE + eb + u] = res[lane] + cbk;
        }

        if (!has_next) break;
        g += W;  b = bn;  eb = ebn;
        bn = bn2; ebn = ebn2; gan = ga2; gbn = gb2;
        s ^= 1;
    }

    // drain outstanding copies before exit
    asm volatile("cp.async.wait_group 0;" ::: "memory");
}

// ---------------------------------------------------------------------------
extern "C" void kernel_launch(void* const* d_in, const int* in_sizes, int n_in,
                              void* d_out, int out_size)
{
    const float* x_0      = (const float*)d_in[0];
    const float* x_1      = (const float*)d_in[1];
    const int*   gemm     = (const int*)  d_in[2];
    const float* Wa_local = (const float*)d_in[3];
    const float* ba_local = (const float*)d_in[4];
    const float* Wb_local = (const float*)d_in[5];
    const float* bb_local = (const float*)d_in[6];
    const float* Wa_tri   = (const float*)d_in[7];
    const float* ba_tri   = (const float*)d_in[8];
    const float* Wb_tri   = (const float*)d_in[9];
    const float* bb_tri   = (const float*)d_in[10];
    const float* Wa_fuse  = (const float*)d_in[11];
    const float* ba_fuse  = (const float*)d_in[12];
    const float* Wb_fuse  = (const float*)d_in[13];
    const float* bb_fuse  = (const float*)d_in[14];
    float* out = (float*)d_out;

    static bool attr_set = false;
    if (!attr_set) {
        cudaFuncSetAttribute(mesh_main_kernel,
                             cudaFuncAttributeMaxDynamicSharedMemorySize,
                             SMEM_MAIN);
        attr_set = true;
    }

    prep_kernel<<<TR_BLOCKS + W_BLOCKS, 256>>>(
        x_0, x_1,
        Wa_local, ba_local, Wb_local, bb_local,
        Wa_tri, ba_tri, Wb_tri, bb_tri,
        Wa_fuse, ba_fuse, Wb_fuse, bb_fuse);

    mesh_main_kernel<<<296, 256, SMEM_MAIN>>>(gemm, out);
}

// round 13
// speedup vs baseline: 1.2357x; 1.0274x over previous
#include <cuda_runtime.h>
#include <cuda_fp16.h>
#include <cstddef>

#define NB 2
#define NC 128
#define TWOC 256
#define NE 60000
#define TR_BLOCKS (2 * NB * 2 * (NE / 32))          // 15000 transpose tiles
#define W_WARPS   (2 * NC * 15 + 3)
#define W_BLOCKS  ((W_WARPS + 7) / 8)
#define GROUPS4   (NB * NE / 4)                      // 30000 4-edge groups

// Transposed inputs in fp16, tensor-interleaved: [b][e][tensor][c] (512B/edge)
__device__ __half g_xti[(size_t)NB * NE * TWOC];
// Effective fused weights: [branch][c][s*3+k] padded to 16
__device__ float g_V[2][NC][16];
__device__ float g_cb[3];

// ---------------------------------------------------------------------------
// Kernel 1 (fused): transpose x->fp16 interleaved + weight folding.
// ---------------------------------------------------------------------------
__global__ void __launch_bounds__(256)
prep_kernel(const float* __restrict__ x0, const float* __restrict__ x1,
    const float* __restrict__ Wa_local, const float* __restrict__ ba_local,
    const float* __restrict__ Wb_local, const float* __restrict__ bb_local,
    const float* __restrict__ Wa_tri,   const float* __restrict__ ba_tri,
    const float* __restrict__ Wb_tri,   const float* __restrict__ bb_tri,
    const float* __restrict__ Wa_fuse,  const float* __restrict__ ba_fuse,
    const float* __restrict__ Wb_fuse,  const float* __restrict__ bb_fuse)
{
    if (blockIdx.x < TR_BLOCKS) {
        __shared__ __half tile[32][66];
        int bx = blockIdx.x;
        const int eb = bx % (NE / 32);  bx /= (NE / 32);
        const int ch = bx & 1;          bx >>= 1;
        const int b  = bx & 1;
        const int tensor = bx >> 1;
        const float* __restrict__ src = tensor ? x1 : x0;
        const int e0 = eb * 32, c0 = ch * 64;
        const int tx = threadIdx.x & 31;
        const int ty = threadIdx.x >> 5;

#pragma unroll
        for (int i = 0; i < 8; i++) {
            int cl = ty + 8 * i;
            tile[tx][cl] = __float2half_rn(
                src[((size_t)b * NC + c0 + cl) * NE + e0 + tx]);
        }
        __syncthreads();
#pragma unroll
        for (int it = 0; it < 4; it++) {
            int e = ty * 4 + it;
            unsigned v = *reinterpret_cast<const unsigned*>(&tile[e][2 * tx]);
            *reinterpret_cast<unsigned*>(
                g_xti + ((size_t)(b * NE + e0 + e)) * TWOC
                      + tensor * NC + c0 + 2 * tx) = v;
        }
        return;
    }

    const int lane = threadIdx.x & 31;
    const int w = (blockIdx.x - TR_BLOCKS) * 8 + (threadIdx.x >> 5);

    if (w < 2 * NC * 15) {
        const int t   = w / (NC * 15);
        const int rem = w - t * (NC * 15);
        const int c   = rem / 15;
        const int sk  = rem - c * 15;
        const int s   = sk / 3;
        const int k   = sk - s * 3;
        const float* Wf = t ? Wb_fuse  : Wa_fuse;
        const float* Wt = t ? Wb_tri   : Wa_tri;
        const float* Wl = t ? Wb_local : Wa_local;
        float acc = 0.f;
#pragma unroll
        for (int j = 0; j < 4; j++) {
            int o = lane + 32 * j;
            acc = fmaf(Wf[k * (2 * NC) + NC + o], Wt[(o * NC + c) * 5 + s], acc);
            if (s == 0)
                acc = fmaf(Wf[k * (2 * NC) + o], Wl[o * NC + c], acc);
        }
#pragma unroll
        for (int off = 16; off; off >>= 1)
            acc += __shfl_xor_sync(0xffffffffu, acc, off);
        if (lane == 0) {
            g_V[t][c][sk] = acc;
            if (sk == 0) g_V[t][c][15] = 0.f;
        }
    } else if (w < 2 * NC * 15 + 3) {
        const int k = w - 2 * NC * 15;
        float acc = 0.f;
#pragma unroll
        for (int j = 0; j < 4; j++) {
            int o = lane + 32 * j;
            acc = fmaf(Wa_fuse[k * 2 * NC + o],      ba_local[o], acc);
            acc = fmaf(Wa_fuse[k * 2 * NC + NC + o], ba_tri[o],   acc);
            acc = fmaf(Wb_fuse[k * 2 * NC + o],      bb_local[o], acc);
            acc = fmaf(Wb_fuse[k * 2 * NC + NC + o], bb_tri[o],   acc);
        }
#pragma unroll
        for (int off = 16; off; off >>= 1)
            acc += __shfl_xor_sync(0xffffffffu, acc, off);
        if (lane == 0)
            g_cb[k] = acc + ba_fuse[k] + bb_fuse[k];
    }
}

// ---------------------------------------------------------------------------
// Kernel 2: main gather + fused dot over the interleaved layout.
// One warp per 4 edges; one LDG.128.CG per 512B row (L2-only caching —
// no L1 line allocation for the random 30MB gather stream).
// Lane 0-15 -> tensor0 channels 8L.., lane 16-31 -> tensor1.
// ---------------------------------------------------------------------------
__device__ __forceinline__ __half2 u2h(const unsigned& u)
{
    return *reinterpret_cast<const __half2*>(&u);
}

__device__ __forceinline__ void edge_dot(
    const uint4 r0, const uint4 r1, const uint4 r2,
    const uint4 r3, const uint4 r4,
    const __half2 Vp[4][15], float* __restrict__ res)
{
    const __half2 z = __float2half2_rn(0.f);
    __half2 A0 = z, A1 = z, A2 = z, B0 = z, B1 = z, B2 = z;

#define DO_SLOT(j, X0, X1, X2, X3, X4, P0, P1, P2)                        \
    {                                                                     \
        __half2 G0 = u2h(X0);                                             \
        __half2 n1 = u2h(X1), n2 = u2h(X2), n3 = u2h(X3), n4 = u2h(X4);   \
        __half2 G1 = __hadd2(n1, n3), G2 = __hadd2(n2, n4);               \
        __half2 G3 = __habs2(__hsub2(n1, n3));                            \
        __half2 G4 = __habs2(__hsub2(n2, n4));                            \
        P0 = __hfma2(Vp[j][0],  G0, P0);                                  \
        P1 = __hfma2(Vp[j][1],  G0, P1);                                  \
        P2 = __hfma2(Vp[j][2],  G0, P2);                                  \
        P0 = __hfma2(Vp[j][3],  G1, P0);                                  \
        P1 = __hfma2(Vp[j][4],  G1, P1);                                  \
        P2 = __hfma2(Vp[j][5],  G1, P2);                                  \
        P0 = __hfma2(Vp[j][6],  G2, P0);                                  \
        P1 = __hfma2(Vp[j][7],  G2, P1);                                  \
        P2 = __hfma2(Vp[j][8],  G2, P2);                                  \
        P0 = __hfma2(Vp[j][9],  G3, P0);                                  \
        P1 = __hfma2(Vp[j][10], G3, P1);                                  \
        P2 = __hfma2(Vp[j][11], G3, P2);                                  \
        P0 = __hfma2(Vp[j][12], G4, P0);                                  \
        P1 = __hfma2(Vp[j][13], G4, P1);                                  \
        P2 = __hfma2(Vp[j][14], G4, P2);                                  \
    }

    DO_SLOT(0, r0.x, r1.x, r2.x, r3.x, r4.x, A0, A1, A2)
    DO_SLOT(1, r0.y, r1.y, r2.y, r3.y, r4.y, A0, A1, A2)
    DO_SLOT(2, r0.z, r1.z, r2.z, r3.z, r4.z, B0, B1, B2)
    DO_SLOT(3, r0.w, r1.w, r2.w, r3.w, r4.w, B0, B1, B2)
#undef DO_SLOT

    float2 a0 = __half22float2(A0), b0 = __half22float2(B0);
    float2 a1 = __half22float2(A1), b1 = __half22float2(B1);
    float2 a2 = __half22float2(A2), b2 = __half22float2(B2);
    res[0] = (a0.x + a0.y) + (b0.x + b0.y);
    res[1] = (a1.x + a1.y) + (b1.x + b1.y);
    res[2] = (a2.x + a2.y) + (b2.x + b2.y);
}

// one PAIR of edges: 10 batched LDG.128.CG, then two computes -> res[0..5]
__device__ __forceinline__ void do_pair(
    const __half* __restrict__ base,
    int e, const int4 gi0, const int4 gi1,
    const __half2 Vp[4][15], float* __restrict__ res)
{
    uint4 a0 = __ldcg(reinterpret_cast<const uint4*>(base + (size_t)e     * TWOC));
    uint4 a1 = __ldcg(reinterpret_cast<const uint4*>(base + (size_t)gi0.x * TWOC));
    uint4 a2 = __ldcg(reinterpret_cast<const uint4*>(base + (size_t)gi0.y * TWOC));
    uint4 a3 = __ldcg(reinterpret_cast<const uint4*>(base + (size_t)gi0.z * TWOC));
    uint4 a4 = __ldcg(reinterpret_cast<const uint4*>(base + (size_t)gi0.w * TWOC));
    uint4 c0 = __ldcg(reinterpret_cast<const uint4*>(base + (size_t)(e+1) * TWOC));
    uint4 c1 = __ldcg(reinterpret_cast<const uint4*>(base + (size_t)gi1.x * TWOC));
    uint4 c2 = __ldcg(reinterpret_cast<const uint4*>(base + (size_t)gi1.y * TWOC));
    uint4 c3 = __ldcg(reinterpret_cast<const uint4*>(base + (size_t)gi1.z * TWOC));
    uint4 c4 = __ldcg(reinterpret_cast<const uint4*>(base + (size_t)gi1.w * TWOC));

    edge_dot(a0, a1, a2, a3, a4, Vp, res);
    edge_dot(c0, c1, c2, c3, c4, Vp, res + 3);
}

__global__ void __launch_bounds__(256, 2)
mesh_main_kernel(const int* __restrict__ gemm, float* __restrict__ out)
{
    const int lane = threadIdx.x & 31;
    const int gw   = blockIdx.x * 8 + (threadIdx.x >> 5);
    const int W    = gridDim.x * 8;

    const int lt = lane >> 4;              // tensor
    const int lc = (lane & 15) * 8;        // channel base (8 channels)

    __half2 Vp[4][15];
#pragma unroll
    for (int j = 0; j < 4; j++) {
        const float* r0 = g_V[lt][lc + 2 * j];
        const float* r1 = g_V[lt][lc + 2 * j + 1];
#pragma unroll
        for (int sk = 0; sk < 15; sk++)
            Vp[j][sk] = __floats2half2_rn(r0[sk], r1[sk]);
    }
    float cbk = (lane < 12) ? g_cb[lane % 3] : 0.f;

    const int4* __restrict__ gi4 = reinterpret_cast<const int4*>(gemm);

    int g = gw;
    if (g >= GROUPS4) return;

    int e0 = 4 * g;
    int b  = (e0 >= NE) ? 1 : 0;
    int eb = e0 - b * NE;
    int4 gA = gi4[(size_t)b * NE + eb];
    int4 gB = gi4[(size_t)b * NE + eb + 1];

    while (g < GROUPS4) {
        const int4 gC = gi4[(size_t)b * NE + eb + 2];
        const int4 gD = gi4[(size_t)b * NE + eb + 3];

        const int gn  = g + W;
        const int gnc = (gn < GROUPS4) ? gn : gw;
        const int e0n = 4 * gnc;
        const int bn  = (e0n >= NE) ? 1 : 0;
        const int ebn = e0n - bn * NE;
        const int4 gA_n = gi4[(size_t)bn * NE + ebn];
        const int4 gB_n = gi4[(size_t)bn * NE + ebn + 1];

        const __half* __restrict__ base =
            g_xti + (size_t)b * NE * TWOC + lane * 8;

        float res[12];
        do_pair(base, eb,     gA, gB, Vp, res);
        do_pair(base, eb + 2, gC, gD, Vp, res + 6);

#pragma unroll
        for (int off = 16; off; off >>= 1)
#pragma unroll
            for (int r = 0; r < 12; r++)
                res[r] += __shfl_xor_sync(0xffffffffu, res[r], off);

        if (lane < 12) {
            const int u = lane / 3;
            const int k = lane - 3 * u;
            out[((size_t)b * 3 + k) * NE + eb + u] = res[lane] + cbk;
        }

        g  = gn;
        b  = bn;
        eb = ebn;
        gA = gA_n;
        gB = gB_n;
    }
}

// ---------------------------------------------------------------------------
extern "C" void kernel_launch(void* const* d_in, const int* in_sizes, int n_in,
                              void* d_out, int out_size)
{
    const float* x_0      = (const float*)d_in[0];
    const float* x_1      = (const float*)d_in[1];
    const int*   gemm     = (const int*)  d_in[2];
    const float* Wa_local = (const float*)d_in[3];
    const float* ba_local = (const float*)d_in[4];
    const float* Wb_local = (const float*)d_in[5];
    const float* bb_local = (const float*)d_in[6];
    const float* Wa_tri   = (const float*)d_in[7];
    const float* ba_tri   = (const float*)d_in[8];
    const float* Wb_tri   = (const float*)d_in[9];
    const float* bb_tri   = (const float*)d_in[10];
    const float* Wa_fuse  = (const float*)d_in[11];
    const float* ba_fuse  = (const float*)d_in[12];
    const float* Wb_fuse  = (const float*)d_in[13];
    const float* bb_fuse  = (const float*)d_in[14];
    float* out = (float*)d_out;

    prep_kernel<<<TR_BLOCKS + W_BLOCKS, 256>>>(
        x_0, x_1,
        Wa_local, ba_local, Wb_local, bb_local,
        Wa_tri, ba_tri, Wb_tri, bb_tri,
        Wa_fuse, ba_fuse, Wb_fuse, bb_fuse);

    mesh_main_kernel<<<296, 256>>>(gemm, out);
}